// round 3
// baseline (speedup 1.0000x reference)
#include <cuda_runtime.h>
#include <math.h>
#include <stdint.h>

#define F128 128
#define C40  40
#define MAXN 100000
#define MAXE 1600000
#define BN_EPS 1e-5f

// ---------------- scratch (static __device__, no allocs) ----------------
__device__ float g_h[(size_t)MAXN * F128];    // pre-aggregation features (also h3, 40-wide)
__device__ float g_agg[(size_t)MAXN * F128];  // layer1 agg / layer3 agg
__device__ float g_buf[(size_t)MAXN * F128];  // layer2 agg
__device__ float g_deg[MAXN];
__device__ float g_dinvs[MAXN];               // deg^-1/2
__device__ float g_dinv[MAXN];                // deg^-1
__device__ float g_enorm[MAXE];               // per-edge norm
__device__ float g_sum[F128];
__device__ float g_sq[F128];
__device__ float g_scale[F128];
__device__ float g_shift[F128];

// vectorized global float reductions (sm_90+)
__device__ __forceinline__ void red_add_v4(float* addr, float4 v) {
    asm volatile("red.global.add.v4.f32 [%0], {%1, %2, %3, %4};"
                 :: "l"(addr), "f"(v.x), "f"(v.y), "f"(v.z), "f"(v.w) : "memory");
}

// ---------------- degree / norm ----------------
__global__ void zero_deg(int N) {
    int i = blockIdx.x * blockDim.x + threadIdx.x;
    if (i < N) g_deg[i] = 0.f;
}

__global__ void deg_acc(const int* __restrict__ dst, int E) {
    int e = blockIdx.x * blockDim.x + threadIdx.x;
    if (e < E) atomicAdd(&g_deg[dst[e]], 1.f);
}

__global__ void node_norm(int N) {
    int i = blockIdx.x * blockDim.x + threadIdx.x;
    if (i < N) {
        float d = g_deg[i] + 1.f;
        g_dinvs[i] = rsqrtf(d);
        g_dinv[i]  = 1.f / d;
    }
}

__global__ void edge_norm(const int* __restrict__ src, const int* __restrict__ dst, int E) {
    int e = blockIdx.x * blockDim.x + threadIdx.x;
    if (e < E) g_enorm[e] = g_dinvs[src[e]] * g_dinvs[dst[e]];
}

// ---------------- 128x128 GEMM with fused self-loop/bias epilogue ----------------
// Hout = X @ W     (N x 128)
// Agg  = dinv[row]*Hout + bias[col]   (scatter-add target initial value)
__global__ __launch_bounds__(256) void gemm128_epi(
    const float* __restrict__ X, const float* __restrict__ W,
    const float* __restrict__ bias, const float* __restrict__ dinv,
    float* __restrict__ Hout, float* __restrict__ Agg, int N)
{
    __shared__ float As[16][128];
    __shared__ float Bs[16][128];
    const int tid = threadIdx.x;
    const int tx = tid & 15;      // col group
    const int ty = tid >> 4;      // row group
    const int m0 = blockIdx.x * 128;

    float acc[8][8];
#pragma unroll
    for (int i = 0; i < 8; i++)
#pragma unroll
        for (int j = 0; j < 8; j++) acc[i][j] = 0.f;

    for (int k0 = 0; k0 < 128; k0 += 16) {
        // load A tile (128 rows x 16 k), store transposed As[k][m]
#pragma unroll
        for (int it = 0; it < 2; it++) {
            int f  = tid + it * 256;      // 0..511 float4s
            int m  = f >> 2;
            int k4 = f & 3;
            int row = m0 + m;
            float4 v = make_float4(0.f, 0.f, 0.f, 0.f);
            if (row < N) v = *(const float4*)(X + (size_t)row * 128 + k0 + k4 * 4);
            As[k4 * 4 + 0][m] = v.x;
            As[k4 * 4 + 1][m] = v.y;
            As[k4 * 4 + 2][m] = v.z;
            As[k4 * 4 + 3][m] = v.w;
        }
        // load B tile (16 k x 128 n)
#pragma unroll
        for (int it = 0; it < 2; it++) {
            int f  = tid + it * 256;
            int kk = f >> 5;
            int n4 = f & 31;
            *(float4*)&Bs[kk][n4 * 4] = *(const float4*)(W + (size_t)(k0 + kk) * 128 + n4 * 4);
        }
        __syncthreads();
#pragma unroll
        for (int kk = 0; kk < 16; kk++) {
            float a[8], b[8];
            *(float4*)&a[0] = *(const float4*)&As[kk][ty * 8];
            *(float4*)&a[4] = *(const float4*)&As[kk][ty * 8 + 4];
            *(float4*)&b[0] = *(const float4*)&Bs[kk][tx * 8];
            *(float4*)&b[4] = *(const float4*)&Bs[kk][tx * 8 + 4];
#pragma unroll
            for (int i = 0; i < 8; i++)
#pragma unroll
                for (int j = 0; j < 8; j++)
                    acc[i][j] = fmaf(a[i], b[j], acc[i][j]);
        }
        __syncthreads();
    }

#pragma unroll
    for (int i = 0; i < 8; i++) {
        int row = m0 + ty * 8 + i;
        if (row >= N) continue;
        float dv = dinv[row];
#pragma unroll
        for (int j = 0; j < 8; j += 4) {
            int col = tx * 8 + j;
            float4 h;
            h.x = acc[i][j + 0]; h.y = acc[i][j + 1];
            h.z = acc[i][j + 2]; h.w = acc[i][j + 3];
            *(float4*)(Hout + (size_t)row * 128 + col) = h;
            float4 ag;
            ag.x = fmaf(dv, h.x, bias[col + 0]);
            ag.y = fmaf(dv, h.y, bias[col + 1]);
            ag.z = fmaf(dv, h.z, bias[col + 2]);
            ag.w = fmaf(dv, h.w, bias[col + 3]);
            *(float4*)(Agg + (size_t)row * 128 + col) = ag;
        }
    }
}

// ---------------- 128->40 GEMM with fused epilogue ----------------
__global__ __launch_bounds__(320) void gemm40_epi(
    const float* __restrict__ X, const float* __restrict__ W,
    const float* __restrict__ bias, const float* __restrict__ dinv,
    float* __restrict__ Hout, float* __restrict__ Agg, int N)
{
    __shared__ float4 Xs[64 * 32];   // 64 rows x 128 cols
    const int tid = threadIdx.x;     // 320
    const int m0  = blockIdx.x * 64;

    for (int f = tid; f < 64 * 32; f += 320) {
        int m = f >> 5, k4 = f & 31;
        int row = m0 + m;
        float4 v = make_float4(0.f, 0.f, 0.f, 0.f);
        if (row < N) v = *(const float4*)(X + (size_t)row * 128 + k4 * 4);
        Xs[f] = v;
    }
    __syncthreads();

    const int col   = tid % 40;
    const int rbase = tid / 40;   // 0..7
    float acc[8];
#pragma unroll
    for (int i = 0; i < 8; i++) acc[i] = 0.f;

    for (int k4 = 0; k4 < 32; k4++) {
        int k = k4 * 4;
        float w0 = __ldg(W + (size_t)(k + 0) * 40 + col);
        float w1 = __ldg(W + (size_t)(k + 1) * 40 + col);
        float w2 = __ldg(W + (size_t)(k + 2) * 40 + col);
        float w3 = __ldg(W + (size_t)(k + 3) * 40 + col);
#pragma unroll
        for (int i = 0; i < 8; i++) {
            float4 a = Xs[(rbase + 8 * i) * 32 + k4];
            acc[i] = fmaf(a.x, w0, acc[i]);
            acc[i] = fmaf(a.y, w1, acc[i]);
            acc[i] = fmaf(a.z, w2, acc[i]);
            acc[i] = fmaf(a.w, w3, acc[i]);
        }
    }
    float bc = bias[col];
#pragma unroll
    for (int i = 0; i < 8; i++) {
        int row = m0 + rbase + 8 * i;
        if (row < N) {
            Hout[(size_t)row * 40 + col] = acc[i];
            Agg[(size_t)row * 40 + col]  = fmaf(dinv[row], acc[i], bc);
        }
    }
}

// ---------------- edge propagation (scatter-add), one warp per edge ----------------
__global__ void prop128(const float4* __restrict__ h4, const int* __restrict__ src,
                        const int* __restrict__ dst, float* __restrict__ agg, int E)
{
    int w = (blockIdx.x * blockDim.x + threadIdx.x) >> 5;
    int lane = threadIdx.x & 31;
    if (w >= E) return;
    int s   = __ldg(src + w);
    int d   = __ldg(dst + w);
    float nm = __ldg(&g_enorm[w]);
    float4 v = h4[(size_t)s * 32 + lane];
    v.x *= nm; v.y *= nm; v.z *= nm; v.w *= nm;
    red_add_v4(agg + (size_t)d * 128 + lane * 4, v);
}

// 40-wide scatter: 10 float4-chunks per edge, thread-per-(edge,chunk)
__global__ void prop40(const float* __restrict__ h, const int* __restrict__ src,
                       const int* __restrict__ dst, float* __restrict__ agg, int E)
{
    long long idx = (long long)blockIdx.x * blockDim.x + threadIdx.x;
    int e    = (int)(idx / 10);
    int part = (int)(idx % 10);
    if (e >= E) return;
    int s   = __ldg(src + e);
    int d   = __ldg(dst + e);
    float nm = __ldg(&g_enorm[e]);
    float4 v = *(const float4*)(h + (size_t)s * 40 + part * 4);
    v.x *= nm; v.y *= nm; v.z *= nm; v.w *= nm;
    red_add_v4(agg + (size_t)d * 40 + part * 4, v);
}

// ---------------- BatchNorm stats / apply ----------------
__global__ void zero_stats() {
    int c = threadIdx.x;
    g_sum[c] = 0.f;
    g_sq[c]  = 0.f;
}

__global__ void colstats(const float* __restrict__ xin, int N)
{
    int col  = threadIdx.x & 127;
    int half = threadIdx.x >> 7;
    float s = 0.f, q = 0.f;
    for (int r = blockIdx.x * 2 + half; r < N; r += gridDim.x * 2) {
        float v = xin[(size_t)r * 128 + col];
        s += v; q = fmaf(v, v, q);
    }
    __shared__ float ss[256], sq2[256];
    ss[threadIdx.x] = s; sq2[threadIdx.x] = q;
    __syncthreads();
    if (threadIdx.x < 128) {
        atomicAdd(&g_sum[col], ss[threadIdx.x] + ss[threadIdx.x + 128]);
        atomicAdd(&g_sq[col],  sq2[threadIdx.x] + sq2[threadIdx.x + 128]);
    }
}

__global__ void bnparams(const float* __restrict__ g, const float* __restrict__ be, int N)
{
    int c = threadIdx.x;
    float invN = 1.f / (float)N;
    float mean = g_sum[c] * invN;
    float var  = g_sq[c] * invN - mean * mean;
    float sc   = g[c] * rsqrtf(var + BN_EPS);
    g_scale[c] = sc;
    g_shift[c] = be[c] - mean * sc;
}

__global__ void bnrelu(float4* __restrict__ xio, int n4)
{
    int i = blockIdx.x * blockDim.x + threadIdx.x;
    if (i >= n4) return;
    int c4 = i & 31;
    float4 v  = xio[i];
    float4 sc = ((const float4*)g_scale)[c4];
    float4 sh = ((const float4*)g_shift)[c4];
    v.x = fmaxf(fmaf(v.x, sc.x, sh.x), 0.f);
    v.y = fmaxf(fmaf(v.y, sc.y, sh.y), 0.f);
    v.z = fmaxf(fmaf(v.z, sc.z, sh.z), 0.f);
    v.w = fmaxf(fmaf(v.w, sc.w, sh.w), 0.f);
    xio[i] = v;
}

// ---------------- log-softmax over 40 classes, one warp per row ----------------
__global__ void logsoftmax40(const float* __restrict__ in, float* __restrict__ out, int N)
{
    int row  = (blockIdx.x * blockDim.x + threadIdx.x) >> 5;
    int lane = threadIdx.x & 31;
    if (row >= N) return;
    size_t base = (size_t)row * 40;
    float v0 = in[base + lane];
    float v1 = (lane < 8) ? in[base + 32 + lane] : -INFINITY;
    float m  = fmaxf(v0, v1);
#pragma unroll
    for (int o = 16; o; o >>= 1) m = fmaxf(m, __shfl_xor_sync(0xffffffffu, m, o));
    float e = __expf(v0 - m) + ((lane < 8) ? __expf(v1 - m) : 0.f);
#pragma unroll
    for (int o = 16; o; o >>= 1) e += __shfl_xor_sync(0xffffffffu, e, o);
    float ls = m + __logf(e);
    out[base + lane] = v0 - ls;
    if (lane < 8) out[base + 32 + lane] = v1 - ls;
}

// ---------------- launcher ----------------
extern "C" void kernel_launch(void* const* d_in, const int* in_sizes, int n_in,
                              void* d_out, int out_size)
{
    const float* x   = (const float*)d_in[0];
    const float* W1  = (const float*)d_in[1];
    const float* b1  = (const float*)d_in[2];
    const float* W2  = (const float*)d_in[3];
    const float* b2  = (const float*)d_in[4];
    const float* W3  = (const float*)d_in[5];
    const float* b3  = (const float*)d_in[6];
    const float* g1  = (const float*)d_in[7];
    const float* be1 = (const float*)d_in[8];
    const float* g2  = (const float*)d_in[9];
    const float* be2 = (const float*)d_in[10];
    const int*   ei  = (const int*)d_in[11];

    int N = in_sizes[0] / F128;
    int E = in_sizes[11] / 2;
    const int* src = ei;
    const int* dst = ei + E;
    float* out = (float*)d_out;

    // resolve scratch addresses once, outside any graph capture
    static float* hbuf   = nullptr;
    static float* aggbuf = nullptr;
    static float* buf2   = nullptr;
    static float* dinv   = nullptr;
    if (!hbuf) {
        cudaGetSymbolAddress((void**)&hbuf,   g_h);
        cudaGetSymbolAddress((void**)&aggbuf, g_agg);
        cudaGetSymbolAddress((void**)&buf2,   g_buf);
        cudaGetSymbolAddress((void**)&dinv,   g_dinv);
    }

    int nb  = (N + 255) / 256;
    int ebv = (E + 255) / 256;
    int pb  = (E + 7) / 8;       // 8 warps (edges) per 256-thread block
    int gb  = (N + 127) / 128;
    int g40 = (N + 63) / 64;
    int bnb = (N * 32 + 255) / 256;
    int lsb = (N + 7) / 8;
    long long p40t = (long long)E * 10;
    int p40b = (int)((p40t + 319) / 320);

    // graph norm
    zero_deg<<<nb, 256>>>(N);
    deg_acc<<<ebv, 256>>>(dst, E);
    node_norm<<<nb, 256>>>(N);
    edge_norm<<<ebv, 256>>>(src, dst, E);

    // layer 1
    gemm128_epi<<<gb, 256>>>(x, W1, b1, dinv, hbuf, aggbuf, N);
    prop128<<<pb, 256>>>((const float4*)hbuf, src, dst, aggbuf, E);
    zero_stats<<<1, 128>>>();
    colstats<<<512, 256>>>(aggbuf, N);
    bnparams<<<1, 128>>>(g1, be1, N);
    bnrelu<<<bnb, 256>>>((float4*)aggbuf, N * 32);

    // layer 2
    gemm128_epi<<<gb, 256>>>(aggbuf, W2, b2, dinv, hbuf, buf2, N);
    prop128<<<pb, 256>>>((const float4*)hbuf, src, dst, buf2, E);
    zero_stats<<<1, 128>>>();
    colstats<<<512, 256>>>(buf2, N);
    bnparams<<<1, 128>>>(g2, be2, N);
    bnrelu<<<bnb, 256>>>((float4*)buf2, N * 32);

    // layer 3 + log_softmax
    gemm40_epi<<<g40, 320>>>(buf2, W3, b3, dinv, hbuf, aggbuf, N);
    prop40<<<p40b, 320>>>(hbuf, src, dst, aggbuf, E);
    logsoftmax40<<<lsb, 256>>>(aggbuf, out, N);
}

// round 6
// speedup vs baseline: 1.5491x; 1.5491x over previous
#include <cuda_runtime.h>
#include <math.h>
#include <stdint.h>

#define F128 128
#define C40  40
#define MAXN 100000
#define MAXE 1600000
#define BN_EPS 1e-5f
#define SCAN_CHUNK 1024
#define MAXSB ((MAXN + SCAN_CHUNK - 1) / SCAN_CHUNK)

// ---------------- scratch (static __device__, no allocs) ----------------
__device__ float g_h[(size_t)MAXN * F128];
__device__ float g_agg[(size_t)MAXN * F128];
__device__ float g_buf[(size_t)MAXN * F128];
__device__ float g_dinvs[MAXN];               // deg^-1/2
__device__ float g_dinv[MAXN];                // deg^-1
__device__ int   g_cnt[MAXN];                 // in-degree (no self loop)
__device__ int   g_rowptr[MAXN + 1];
__device__ int   g_cursor[MAXN];
__device__ int   g_blocksum[MAXSB + 1];
__device__ int   g_csrc[MAXE];                // CSR src per (dst-sorted) edge
__device__ float g_cnorm[MAXE];               // CSR edge norm
__device__ float g_sum[F128];
__device__ float g_sq[F128];
__device__ float g_scale[F128];
__device__ float g_shift[F128];

__device__ __forceinline__ void red_add_v4(float* addr, float4 v) {
    asm volatile("red.global.add.v4.f32 [%0], {%1, %2, %3, %4};"
                 :: "l"(addr), "f"(v.x), "f"(v.y), "f"(v.z), "f"(v.w) : "memory");
}

// ---------------- CSR build ----------------
__global__ void zero_cnt(int N) {
    int i = blockIdx.x * blockDim.x + threadIdx.x;
    if (i < N) g_cnt[i] = 0;
}

__global__ void count_deg(const int* __restrict__ dst, int E) {
    int e = blockIdx.x * blockDim.x + threadIdx.x;
    if (e < E) atomicAdd(&g_cnt[dst[e]], 1);
}

__global__ void node_norm(int N) {
    int i = blockIdx.x * blockDim.x + threadIdx.x;
    if (i < N) {
        float d = (float)g_cnt[i] + 1.f;
        g_dinvs[i] = rsqrtf(d);
        g_dinv[i]  = 1.f / d;
    }
}

__global__ void scan1(int N) {
    __shared__ int sdata[256];
    int t = threadIdx.x;
    int base = blockIdx.x * SCAN_CHUNK + t * 4;
    int v0 = (base + 0 < N) ? g_cnt[base + 0] : 0;
    int v1 = (base + 1 < N) ? g_cnt[base + 1] : 0;
    int v2 = (base + 2 < N) ? g_cnt[base + 2] : 0;
    int v3 = (base + 3 < N) ? g_cnt[base + 3] : 0;
    int tsum = v0 + v1 + v2 + v3;
    sdata[t] = tsum;
    __syncthreads();
    for (int off = 1; off < 256; off <<= 1) {
        int x = (t >= off) ? sdata[t - off] : 0;
        __syncthreads();
        sdata[t] += x;
        __syncthreads();
    }
    int excl = sdata[t] - tsum;
    if (t == 255) g_blocksum[blockIdx.x] = sdata[255];
    if (base + 0 < N) g_rowptr[base + 0] = excl;
    if (base + 1 < N) g_rowptr[base + 1] = excl + v0;
    if (base + 2 < N) g_rowptr[base + 2] = excl + v0 + v1;
    if (base + 3 < N) g_rowptr[base + 3] = excl + v0 + v1 + v2;
}

__global__ void scan2(int SB, int N) {
    int acc = 0;
    for (int i = 0; i < SB; i++) {
        int v = g_blocksum[i];
        g_blocksum[i] = acc;
        acc += v;
    }
    g_rowptr[N] = acc;   // == E
}

__global__ void scan3(int N) {
    int i = blockIdx.x * blockDim.x + threadIdx.x;
    if (i < N) {
        g_rowptr[i] += g_blocksum[i / SCAN_CHUNK];
        g_cursor[i] = 0;
    }
}

__global__ void csr_fill(const int* __restrict__ src, const int* __restrict__ dst, int E) {
    int e = blockIdx.x * blockDim.x + threadIdx.x;
    if (e >= E) return;
    int s = src[e], d = dst[e];
    int pos = g_rowptr[d] + atomicAdd(&g_cursor[d], 1);
    g_csrc[pos]  = s;
    g_cnorm[pos] = g_dinvs[s] * g_dinvs[d];
}

// ---------------- 128x128 GEMM, optional fused BN+ReLU on A, self-loop epilogue ----------------
__global__ __launch_bounds__(256) void gemm128_epi(
    const float* __restrict__ X, const float* __restrict__ W,
    const float* __restrict__ bias, const float* __restrict__ dinv,
    float* __restrict__ Hout, float* __restrict__ Agg, int N, int bn)
{
    __shared__ float As[16][128];
    __shared__ float Bs[16][128];
    const int tid = threadIdx.x;
    const int tx = tid & 15;
    const int ty = tid >> 4;
    const int m0 = blockIdx.x * 128;

    float acc[8][8];
#pragma unroll
    for (int i = 0; i < 8; i++)
#pragma unroll
        for (int j = 0; j < 8; j++) acc[i][j] = 0.f;

    for (int k0 = 0; k0 < 128; k0 += 16) {
#pragma unroll
        for (int it = 0; it < 2; it++) {
            int f  = tid + it * 256;
            int m  = f >> 2;
            int k4 = f & 3;
            int row = m0 + m;
            int col = k0 + k4 * 4;
            float4 v = make_float4(0.f, 0.f, 0.f, 0.f);
            if (row < N) v = *(const float4*)(X + (size_t)row * 128 + col);
            if (bn) {
                float4 sc = *(const float4*)&g_scale[col];
                float4 sh = *(const float4*)&g_shift[col];
                v.x = fmaxf(fmaf(v.x, sc.x, sh.x), 0.f);
                v.y = fmaxf(fmaf(v.y, sc.y, sh.y), 0.f);
                v.z = fmaxf(fmaf(v.z, sc.z, sh.z), 0.f);
                v.w = fmaxf(fmaf(v.w, sc.w, sh.w), 0.f);
            }
            As[k4 * 4 + 0][m] = v.x;
            As[k4 * 4 + 1][m] = v.y;
            As[k4 * 4 + 2][m] = v.z;
            As[k4 * 4 + 3][m] = v.w;
        }
#pragma unroll
        for (int it = 0; it < 2; it++) {
            int f  = tid + it * 256;
            int kk = f >> 5;
            int n4 = f & 31;
            *(float4*)&Bs[kk][n4 * 4] = *(const float4*)(W + (size_t)(k0 + kk) * 128 + n4 * 4);
        }
        __syncthreads();
#pragma unroll
        for (int kk = 0; kk < 16; kk++) {
            float a[8], b[8];
            *(float4*)&a[0] = *(const float4*)&As[kk][ty * 8];
            *(float4*)&a[4] = *(const float4*)&As[kk][ty * 8 + 4];
            *(float4*)&b[0] = *(const float4*)&Bs[kk][tx * 8];
            *(float4*)&b[4] = *(const float4*)&Bs[kk][tx * 8 + 4];
#pragma unroll
            for (int i = 0; i < 8; i++)
#pragma unroll
                for (int j = 0; j < 8; j++)
                    acc[i][j] = fmaf(a[i], b[j], acc[i][j]);
        }
        __syncthreads();
    }

#pragma unroll
    for (int i = 0; i < 8; i++) {
        int row = m0 + ty * 8 + i;
        if (row >= N) continue;
        float dv = dinv[row];
#pragma unroll
        for (int j = 0; j < 8; j += 4) {
            int col = tx * 8 + j;
            float4 h;
            h.x = acc[i][j + 0]; h.y = acc[i][j + 1];
            h.z = acc[i][j + 2]; h.w = acc[i][j + 3];
            *(float4*)(Hout + (size_t)row * 128 + col) = h;
            float4 ag;
            ag.x = fmaf(dv, h.x, bias[col + 0]);
            ag.y = fmaf(dv, h.y, bias[col + 1]);
            ag.z = fmaf(dv, h.z, bias[col + 2]);
            ag.w = fmaf(dv, h.w, bias[col + 3]);
            *(float4*)(Agg + (size_t)row * 128 + col) = ag;
        }
    }
}

// ---------------- 128->40 GEMM, fused BN+ReLU on A, self-loop epilogue ----------------
__global__ __launch_bounds__(320) void gemm40_epi(
    const float* __restrict__ X, const float* __restrict__ W,
    const float* __restrict__ bias, const float* __restrict__ dinv,
    float* __restrict__ Hout, float* __restrict__ Agg, int N)
{
    __shared__ float4 Xs[64 * 32];
    const int tid = threadIdx.x;
    const int m0  = blockIdx.x * 64;

    for (int f = tid; f < 64 * 32; f += 320) {
        int m = f >> 5, k4 = f & 31;
        int row = m0 + m;
        float4 v = make_float4(0.f, 0.f, 0.f, 0.f);
        if (row < N) v = *(const float4*)(X + (size_t)row * 128 + k4 * 4);
        float4 sc = *(const float4*)&g_scale[k4 * 4];
        float4 sh = *(const float4*)&g_shift[k4 * 4];
        v.x = fmaxf(fmaf(v.x, sc.x, sh.x), 0.f);
        v.y = fmaxf(fmaf(v.y, sc.y, sh.y), 0.f);
        v.z = fmaxf(fmaf(v.z, sc.z, sh.z), 0.f);
        v.w = fmaxf(fmaf(v.w, sc.w, sh.w), 0.f);
        Xs[f] = v;
    }
    __syncthreads();

    const int col   = tid % 40;
    const int rbase = tid / 40;
    float acc[8];
#pragma unroll
    for (int i = 0; i < 8; i++) acc[i] = 0.f;

    for (int k4 = 0; k4 < 32; k4++) {
        int k = k4 * 4;
        float w0 = __ldg(W + (size_t)(k + 0) * 40 + col);
        float w1 = __ldg(W + (size_t)(k + 1) * 40 + col);
        float w2 = __ldg(W + (size_t)(k + 2) * 40 + col);
        float w3 = __ldg(W + (size_t)(k + 3) * 40 + col);
#pragma unroll
        for (int i = 0; i < 8; i++) {
            float4 a = Xs[(rbase + 8 * i) * 32 + k4];
            acc[i] = fmaf(a.x, w0, acc[i]);
            acc[i] = fmaf(a.y, w1, acc[i]);
            acc[i] = fmaf(a.z, w2, acc[i]);
            acc[i] = fmaf(a.w, w3, acc[i]);
        }
    }
    float bc = bias[col];
#pragma unroll
    for (int i = 0; i < 8; i++) {
        int row = m0 + rbase + 8 * i;
        if (row < N) {
            Hout[(size_t)row * 40 + col] = acc[i];
            Agg[(size_t)row * 40 + col]  = fmaf(dinv[row], acc[i], bc);
        }
    }
}

// ---------------- CSR gather-aggregation (128-wide), optional fused BN stats ----------------
__global__ __launch_bounds__(256) void agg128(
    const float4* __restrict__ h4, float* __restrict__ agg, int N, int stats)
{
    const int lane  = threadIdx.x & 31;
    const int wid   = (blockIdx.x * blockDim.x + threadIdx.x) >> 5;
    const int nwarp = (gridDim.x * blockDim.x) >> 5;

    float4 s4 = make_float4(0.f, 0.f, 0.f, 0.f);
    float4 q4 = make_float4(0.f, 0.f, 0.f, 0.f);

    for (int n = wid; n < N; n += nwarp) {
        int beg = g_rowptr[n], end = g_rowptr[n + 1];
        float4 acc = *(float4*)(agg + (size_t)n * 128 + lane * 4);
        int e = beg;
        for (; e + 4 <= end; e += 4) {
            int   sA = __ldg(&g_csrc[e + 0]), sB = __ldg(&g_csrc[e + 1]);
            int   sC = __ldg(&g_csrc[e + 2]), sD = __ldg(&g_csrc[e + 3]);
            float nA = __ldg(&g_cnorm[e + 0]), nB = __ldg(&g_cnorm[e + 1]);
            float nC = __ldg(&g_cnorm[e + 2]), nD = __ldg(&g_cnorm[e + 3]);
            float4 vA = __ldg(&h4[(size_t)sA * 32 + lane]);
            float4 vB = __ldg(&h4[(size_t)sB * 32 + lane]);
            float4 vC = __ldg(&h4[(size_t)sC * 32 + lane]);
            float4 vD = __ldg(&h4[(size_t)sD * 32 + lane]);
            acc.x = fmaf(nA, vA.x, acc.x); acc.y = fmaf(nA, vA.y, acc.y);
            acc.z = fmaf(nA, vA.z, acc.z); acc.w = fmaf(nA, vA.w, acc.w);
            acc.x = fmaf(nB, vB.x, acc.x); acc.y = fmaf(nB, vB.y, acc.y);
            acc.z = fmaf(nB, vB.z, acc.z); acc.w = fmaf(nB, vB.w, acc.w);
            acc.x = fmaf(nC, vC.x, acc.x); acc.y = fmaf(nC, vC.y, acc.y);
            acc.z = fmaf(nC, vC.z, acc.z); acc.w = fmaf(nC, vC.w, acc.w);
            acc.x = fmaf(nD, vD.x, acc.x); acc.y = fmaf(nD, vD.y, acc.y);
            acc.z = fmaf(nD, vD.z, acc.z); acc.w = fmaf(nD, vD.w, acc.w);
        }
        for (; e < end; e++) {
            int   s = __ldg(&g_csrc[e]);
            float nm = __ldg(&g_cnorm[e]);
            float4 v = __ldg(&h4[(size_t)s * 32 + lane]);
            acc.x = fmaf(nm, v.x, acc.x); acc.y = fmaf(nm, v.y, acc.y);
            acc.z = fmaf(nm, v.z, acc.z); acc.w = fmaf(nm, v.w, acc.w);
        }
        *(float4*)(agg + (size_t)n * 128 + lane * 4) = acc;
        if (stats) {
            s4.x += acc.x; s4.y += acc.y; s4.z += acc.z; s4.w += acc.w;
            q4.x = fmaf(acc.x, acc.x, q4.x); q4.y = fmaf(acc.y, acc.y, q4.y);
            q4.z = fmaf(acc.z, acc.z, q4.z); q4.w = fmaf(acc.w, acc.w, q4.w);
        }
    }

    if (stats) {
        __shared__ float ssum[128], ssq[128];
        if (threadIdx.x < 128) { ssum[threadIdx.x] = 0.f; ssq[threadIdx.x] = 0.f; }
        __syncthreads();
        atomicAdd(&ssum[lane * 4 + 0], s4.x); atomicAdd(&ssum[lane * 4 + 1], s4.y);
        atomicAdd(&ssum[lane * 4 + 2], s4.z); atomicAdd(&ssum[lane * 4 + 3], s4.w);
        atomicAdd(&ssq[lane * 4 + 0], q4.x);  atomicAdd(&ssq[lane * 4 + 1], q4.y);
        atomicAdd(&ssq[lane * 4 + 2], q4.z);  atomicAdd(&ssq[lane * 4 + 3], q4.w);
        __syncthreads();
        if (threadIdx.x < 32) {
            red_add_v4(&g_sum[threadIdx.x * 4], *(float4*)&ssum[threadIdx.x * 4]);
            red_add_v4(&g_sq[threadIdx.x * 4],  *(float4*)&ssq[threadIdx.x * 4]);
        }
    }
}

// ---------------- CSR gather-aggregation (40-wide) ----------------
__global__ void agg40(const float* __restrict__ h, float* __restrict__ agg, int N)
{
    long long idx = (long long)blockIdx.x * blockDim.x + threadIdx.x;
    int n = (int)(idx / 10);
    int c = (int)(idx % 10);
    if (n >= N) return;
    int beg = g_rowptr[n], end = g_rowptr[n + 1];
    float4 acc = *(float4*)(agg + (size_t)n * 40 + c * 4);
    for (int e = beg; e < end; e++) {
        int   s  = __ldg(&g_csrc[e]);
        float nm = __ldg(&g_cnorm[e]);
        float4 v = *(const float4*)(h + (size_t)s * 40 + c * 4);
        acc.x = fmaf(nm, v.x, acc.x); acc.y = fmaf(nm, v.y, acc.y);
        acc.z = fmaf(nm, v.z, acc.z); acc.w = fmaf(nm, v.w, acc.w);
    }
    *(float4*)(agg + (size_t)n * 40 + c * 4) = acc;
}

// ---------------- BN params ----------------
__global__ void zero_stats() {
    int c = threadIdx.x;
    g_sum[c] = 0.f;
    g_sq[c]  = 0.f;
}

__global__ void bnparams(const float* __restrict__ g, const float* __restrict__ be, int N)
{
    int c = threadIdx.x;
    float invN = 1.f / (float)N;
    float mean = g_sum[c] * invN;
    float var  = g_sq[c] * invN - mean * mean;
    float sc   = g[c] * rsqrtf(var + BN_EPS);
    g_scale[c] = sc;
    g_shift[c] = be[c] - mean * sc;
}

// ---------------- log-softmax over 40 classes, one warp per row ----------------
__global__ void logsoftmax40(const float* __restrict__ in, float* __restrict__ out, int N)
{
    int row  = (blockIdx.x * blockDim.x + threadIdx.x) >> 5;
    int lane = threadIdx.x & 31;
    if (row >= N) return;
    size_t base = (size_t)row * 40;
    float v0 = in[base + lane];
    float v1 = (lane < 8) ? in[base + 32 + lane] : -INFINITY;
    float m  = fmaxf(v0, v1);
#pragma unroll
    for (int o = 16; o; o >>= 1) m = fmaxf(m, __shfl_xor_sync(0xffffffffu, m, o));
    float e = __expf(v0 - m) + ((lane < 8) ? __expf(v1 - m) : 0.f);
#pragma unroll
    for (int o = 16; o; o >>= 1) e += __shfl_xor_sync(0xffffffffu, e, o);
    float ls = m + __logf(e);
    out[base + lane] = v0 - ls;
    if (lane < 8) out[base + 32 + lane] = v1 - ls;
}

// ---------------- launcher ----------------
extern "C" void kernel_launch(void* const* d_in, const int* in_sizes, int n_in,
                              void* d_out, int out_size)
{
    const float* x   = (const float*)d_in[0];
    const float* W1  = (const float*)d_in[1];
    const float* b1  = (const float*)d_in[2];
    const float* W2  = (const float*)d_in[3];
    const float* b2  = (const float*)d_in[4];
    const float* W3  = (const float*)d_in[5];
    const float* b3  = (const float*)d_in[6];
    const float* g1  = (const float*)d_in[7];
    const float* be1 = (const float*)d_in[8];
    const float* g2  = (const float*)d_in[9];
    const float* be2 = (const float*)d_in[10];
    const int*   ei  = (const int*)d_in[11];

    int N = in_sizes[0] / F128;
    int E = in_sizes[11] / 2;
    const int* src = ei;
    const int* dst = ei + E;
    float* out = (float*)d_out;

    static float* hbuf   = nullptr;
    static float* aggbuf = nullptr;
    static float* buf2   = nullptr;
    static float* dinv   = nullptr;
    if (!hbuf) {
        cudaGetSymbolAddress((void**)&hbuf,   g_h);
        cudaGetSymbolAddress((void**)&aggbuf, g_agg);
        cudaGetSymbolAddress((void**)&buf2,   g_buf);
        cudaGetSymbolAddress((void**)&dinv,   g_dinv);
    }

    int nb  = (N + 255) / 256;
    int ebv = (E + 255) / 256;
    int gb  = (N + 127) / 128;
    int g40 = (N + 63) / 64;
    int lsb = (N + 7) / 8;
    int SB  = (N + SCAN_CHUNK - 1) / SCAN_CHUNK;
    int aggb = 2368;   // 16 blocks/SM x 148
    long long a40t = (long long)N * 10;
    int a40b = (int)((a40t + 319) / 320);

    // ---- CSR build + norms ----
    zero_cnt<<<nb, 256>>>(N);
    count_deg<<<ebv, 256>>>(dst, E);
    node_norm<<<nb, 256>>>(N);
    scan1<<<SB, 256>>>(N);
    scan2<<<1, 1>>>(SB, N);
    scan3<<<nb, 256>>>(N);
    csr_fill<<<ebv, 256>>>(src, dst, E);

    // ---- layer 1 ----
    zero_stats<<<1, 128>>>();
    gemm128_epi<<<gb, 256>>>(x, W1, b1, dinv, hbuf, aggbuf, N, 0);
    agg128<<<aggb, 256>>>((const float4*)hbuf, aggbuf, N, 1);
    bnparams<<<1, 128>>>(g1, be1, N);

    // ---- layer 2 (BN1+ReLU fused into A-load) ----
    gemm128_epi<<<gb, 256>>>(aggbuf, W2, b2, dinv, hbuf, buf2, N, 1);
    zero_stats<<<1, 128>>>();
    agg128<<<aggb, 256>>>((const float4*)hbuf, buf2, N, 1);
    bnparams<<<1, 128>>>(g2, be2, N);

    // ---- layer 3 (BN2+ReLU fused into A-load) + log_softmax ----
    gemm40_epi<<<g40, 320>>>(buf2, W3, b3, dinv, hbuf, aggbuf, N);
    agg40<<<a40b, 320>>>(hbuf, aggbuf, N);
    logsoftmax40<<<lsb, 256>>>(aggbuf, out, N);
}